// round 16
// baseline (speedup 1.0000x reference)
#include <cuda_runtime.h>
#include <cuda_fp16.h>
#include <math.h>
#include <stdint.h>

#define H   128
#define H2  256
#define H3  384
#define WMC 257          // W_msg columns = 2H+1

#define MAXN 50000
#define MAXE 800000
#define MAXT 4
#define MAXNB ((MAXN + 1023) / 1024)

// ---------------- scratch (static device globals; no allocation) ----------------
// Packed fp16 hi/lo, DE-INTERLEAVED per row: [K/2 H-words | K/2 L-words]
__device__ uint32_t g_hvP [(size_t)MAXN * H];   // hv packed
__device__ uint32_t g_dhvP[(size_t)MAXN * H];   // deg*hv packed
__device__ uint32_t g_SP  [(size_t)MAXN * H];   // gathered S packed
__device__ float    g_gi  [(size_t)MAXN * H3];
__device__ float    g_gh  [(size_t)MAXN * H3];
__device__ float    g_h0  [(size_t)MAXN * H];
__device__ float    g_h1  [(size_t)MAXN * H];
__device__ float    g_deg [MAXN];
__device__ float    g_se  [MAXN];
__device__ float    g_Wc  [(size_t)MAXT * H3 * H2];  // fold intermediate (fp32)
__device__ uint32_t g_WcP [(size_t)MAXT * H3 * H2];  // Wc packed (row: 128 H + 128 L)
__device__ uint32_t g_WhhP[(size_t)MAXT * H3 * H];   // W_hh packed (row: 64 H + 64 L)
__device__ float    g_u1  [MAXT * H3];
__device__ float    g_u2  [MAXT * H3];
__device__ int      g_off [MAXN + 1];
__device__ int      g_cur [MAXN];
__device__ int      g_csrc[MAXE];
__device__ int      g_bsum[MAXNB];
__device__ int      g_bpre[MAXNB];

__device__ __forceinline__ void split_h2(float x, float y, uint32_t& hi, uint32_t& lo) {
    __half hx = __float2half_rn(x);
    __half hy = __float2half_rn(y);
    __half lx = __float2half_rn(x - __half2float(hx));
    __half ly = __float2half_rn(y - __half2float(hy));
    __half2 h = __halves2half2(hx, hy);
    __half2 l = __halves2half2(lx, ly);
    hi = *(uint32_t*)&h;
    lo = *(uint32_t*)&l;
}

// ---------------- utility ----------------
__global__ void zero2_kernel(float* __restrict__ p, float* __restrict__ q, int n) {
    int i = blockIdx.x * blockDim.x + threadIdx.x;
    int stride = gridDim.x * blockDim.x;
    for (int k = i; k < n; k += stride) { p[k] = 0.f; q[k] = 0.f; }
}

__global__ void degse_kernel(const int* __restrict__ dst, const float* __restrict__ he, int E) {
    int e = blockIdx.x * blockDim.x + threadIdx.x;
    if (e >= E) return;
    int d = dst[e];
    atomicAdd(&g_deg[d], 1.0f);
    atomicAdd(&g_se[d], he[e]);
}

// ---------------- CSR prefix scan: multi-block ----------------
__global__ void scan1_kernel(int N) {
    __shared__ int wsum[32];
    int i = blockIdx.x * 1024 + threadIdx.x;
    int lane = threadIdx.x & 31, wid = threadIdx.x >> 5;
    int v = (i < N) ? (int)g_deg[i] : 0;
    int x = v;
    #pragma unroll
    for (int o = 1; o < 32; o <<= 1) {
        int t = __shfl_up_sync(0xFFFFFFFFu, x, o);
        if (lane >= o) x += t;
    }
    if (lane == 31) wsum[wid] = x;
    __syncthreads();
    if (wid == 0) {
        int s = wsum[lane];
        #pragma unroll
        for (int o = 1; o < 32; o <<= 1) {
            int t = __shfl_up_sync(0xFFFFFFFFu, s, o);
            if (lane >= o) s += t;
        }
        wsum[lane] = s;
    }
    __syncthreads();
    int wpre = (wid == 0) ? 0 : wsum[wid - 1];
    if (i < N) g_off[i] = wpre + x - v;
    if (threadIdx.x == 1023) g_bsum[blockIdx.x] = wpre + x;
}

__global__ void scan2_kernel(int nb) {
    if (threadIdx.x == 0) {
        int s = 0;
        for (int b = 0; b < nb; b++) { int t = g_bsum[b]; g_bpre[b] = s; s += t; }
    }
}

__global__ void scan3_kernel(int N, int E) {
    int i = blockIdx.x * 1024 + threadIdx.x;
    if (i < N) {
        int o = g_off[i] + g_bpre[blockIdx.x];
        g_off[i] = o;
        g_cur[i] = o;
    }
    if (i == 0) g_off[N] = E;
}

__global__ void fill_kernel(const int* __restrict__ src, const int* __restrict__ dst, int E) {
    int e = blockIdx.x * blockDim.x + threadIdx.x;
    if (e >= E) return;
    int pos = atomicAdd(&g_cur[dst[e]], 1);
    g_csrc[pos] = src[e];
}

// ---------------- weight folding + packing ----------------
__global__ void fold_wc_kernel(const float* __restrict__ W_ih, const float* __restrict__ W_msg, int T) {
    long idx = (long)blockIdx.x * blockDim.x + threadIdx.x;
    if (idx >= (long)T * H3 * H2) return;
    int k = (int)(idx % H2);
    int j = (int)((idx / H2) % H3);
    int t = (int)(idx / ((long)H2 * H3));
    const float* wi = W_ih + ((size_t)t * H3 + j) * H2;
    const float* wm = W_msg + (size_t)t * H2 * WMC + k;
    float a0 = 0.f, a1 = 0.f, a2 = 0.f, a3 = 0.f;
    #pragma unroll 2
    for (int i = 0; i < H2; i += 4) {
        a0 += __ldg(wi + i)     * __ldg(wm + (size_t)(i)     * WMC);
        a1 += __ldg(wi + i + 1) * __ldg(wm + (size_t)(i + 1) * WMC);
        a2 += __ldg(wi + i + 2) * __ldg(wm + (size_t)(i + 2) * WMC);
        a3 += __ldg(wi + i + 3) * __ldg(wm + (size_t)(i + 3) * WMC);
    }
    g_Wc[idx] = (a0 + a1) + (a2 + a3);
}

// pack weights de-interleaved: Wc rows (128 pairs), Whh rows (64 pairs)
__global__ void pack_w_kernel(const float* __restrict__ W_hh, int T) {
    int i = blockIdx.x * blockDim.x + threadIdx.x;
    int totWc = T * H3 * 128;
    int totWh = T * H3 * 64;
    if (i < totWc) {
        int p = i % 128;
        int row = i / 128;
        float2 v = ((const float2*)g_Wc)[(size_t)row * 128 + p];
        uint32_t h, l;
        split_h2(v.x, v.y, h, l);
        uint32_t* rp = g_WcP + (size_t)row * H2;
        rp[p] = h;
        rp[128 + p] = l;
    } else if (i < totWc + totWh) {
        int j = i - totWc;
        int p = j % 64;
        int row = j / 64;
        float2 v = ((const float2*)W_hh)[(size_t)row * 64 + p];
        uint32_t h, l;
        split_h2(v.x, v.y, h, l);
        uint32_t* rp = g_WhhP + (size_t)row * H;
        rp[p] = h;
        rp[64 + p] = l;
    }
}

__global__ void fold_u_kernel(const float* __restrict__ W_ih, const float* __restrict__ W_msg,
                              const float* __restrict__ b_msg, int T) {
    int idx = blockIdx.x * blockDim.x + threadIdx.x;
    if (idx >= T * H3) return;
    int j = idx % H3, t = idx / H3;
    const float* wi = W_ih + ((size_t)t * H3 + j) * H2;
    const float* wm = W_msg + (size_t)t * H2 * WMC;
    const float* bm = b_msg + (size_t)t * H2;
    float a1 = 0.f, a2 = 0.f;
    for (int i = 0; i < H2; i++) {
        float w = wi[i];
        a1 += w * wm[(size_t)i * WMC + H2];
        a2 += w * bm[i];
    }
    g_u1[idx] = a1;
    g_u2[idx] = a2;
}

// ---------------- split initial hv (and deg*hv), de-interleaved ----------------
__global__ void split0_kernel(const float* __restrict__ hv, int N) {
    int idx = blockIdx.x * blockDim.x + threadIdx.x;
    if (idx >= N * 32) return;
    int n = idx >> 5, q = idx & 31;
    float4 v = ((const float4*)(hv + (size_t)n * H))[q];
    float d = g_deg[n];
    uint32_t h0, l0, h1, l1;
    uint32_t* rp = g_hvP + (size_t)n * H;
    split_h2(v.x, v.y, h0, l0);
    split_h2(v.z, v.w, h1, l1);
    ((uint2*)rp)[q] = make_uint2(h0, h1);
    ((uint2*)(rp + 64))[q] = make_uint2(l0, l1);
    rp = g_dhvP + (size_t)n * H;
    split_h2(d * v.x, d * v.y, h0, l0);
    split_h2(d * v.z, d * v.w, h1, l1);
    ((uint2*)rp)[q] = make_uint2(h0, h1);
    ((uint2*)(rp + 64))[q] = make_uint2(l0, l1);
}

// ---------------- gather: S[n] = sum hv[csrc[e]] (fp32 reads), packed write -------
__global__ void gather_kernel(const float* __restrict__ hv, int N) {
    int n = (blockIdx.x * blockDim.x + threadIdx.x) >> 5;
    int lane = threadIdx.x & 31;
    if (n >= N) return;
    int beg = g_off[n], end = g_off[n + 1];
    float4 acc0 = make_float4(0.f, 0.f, 0.f, 0.f);
    float4 acc1 = make_float4(0.f, 0.f, 0.f, 0.f);
    float4 acc2 = make_float4(0.f, 0.f, 0.f, 0.f);
    float4 acc3 = make_float4(0.f, 0.f, 0.f, 0.f);
    int e = beg;
    for (; e + 4 <= end; e += 4) {
        int s0 = __ldg(g_csrc + e);
        int s1 = __ldg(g_csrc + e + 1);
        int s2 = __ldg(g_csrc + e + 2);
        int s3 = __ldg(g_csrc + e + 3);
        float4 v0 = *(((const float4*)(hv + (size_t)s0 * H)) + lane);
        float4 v1 = *(((const float4*)(hv + (size_t)s1 * H)) + lane);
        float4 v2 = *(((const float4*)(hv + (size_t)s2 * H)) + lane);
        float4 v3 = *(((const float4*)(hv + (size_t)s3 * H)) + lane);
        acc0.x += v0.x; acc0.y += v0.y; acc0.z += v0.z; acc0.w += v0.w;
        acc1.x += v1.x; acc1.y += v1.y; acc1.z += v1.z; acc1.w += v1.w;
        acc2.x += v2.x; acc2.y += v2.y; acc2.z += v2.z; acc2.w += v2.w;
        acc3.x += v3.x; acc3.y += v3.y; acc3.z += v3.z; acc3.w += v3.w;
    }
    for (; e < end; e++) {
        int s0 = __ldg(g_csrc + e);
        float4 v0 = *(((const float4*)(hv + (size_t)s0 * H)) + lane);
        acc0.x += v0.x; acc0.y += v0.y; acc0.z += v0.z; acc0.w += v0.w;
    }
    acc0.x += acc1.x; acc0.y += acc1.y; acc0.z += acc1.z; acc0.w += acc1.w;
    acc2.x += acc3.x; acc2.y += acc3.y; acc2.z += acc3.z; acc2.w += acc3.w;
    acc0.x += acc2.x; acc0.y += acc2.y; acc0.z += acc2.z; acc0.w += acc2.w;
    uint32_t h0, l0, h1, l1;
    split_h2(acc0.x, acc0.y, h0, l0);
    split_h2(acc0.z, acc0.w, h1, l1);
    uint32_t* rp = g_SP + (size_t)n * H;
    ((uint2*)rp)[lane] = make_uint2(h0, h1);
    ((uint2*)(rp + 64))[lane] = make_uint2(l0, l1);
}

// ---------------- 3xFP16 tensor-core GEMM (NT), cp.async 3-stage + ldmatrix, BK=32 -
// Stage: A_H/A_L/B_H/B_L, each [128 rows][pitch 80B, 64B data] = 10240B; stage 40KB.
// Pitch 80B: 80*r mod 128 covers all eight 16B quads -> ldmatrix conflict-free.
#define STG_BYTES 40960u
#define A_L_OFF 10240u
#define B_H_OFF 20480u
#define B_L_OFF 30720u
#define GEMM_SMEM (3 * 40960)

__device__ __forceinline__ void mma_f16(float* acc, const uint32_t* a, const uint32_t* b) {
    asm volatile(
        "mma.sync.aligned.m16n8k16.row.col.f32.f16.f16.f32 "
        "{%0,%1,%2,%3}, {%4,%5,%6,%7}, {%8,%9}, {%0,%1,%2,%3};"
        : "+f"(acc[0]), "+f"(acc[1]), "+f"(acc[2]), "+f"(acc[3])
        : "r"(a[0]), "r"(a[1]), "r"(a[2]), "r"(a[3]), "r"(b[0]), "r"(b[1]));
}

__device__ __forceinline__ void ldsm_x4(uint32_t* r, uint32_t addr) {
    asm volatile("ldmatrix.sync.aligned.m8n8.x4.shared.b16 {%0,%1,%2,%3}, [%4];"
        : "=r"(r[0]), "=r"(r[1]), "=r"(r[2]), "=r"(r[3]) : "r"(addr));
}
__device__ __forceinline__ void ldsm_x2(uint32_t* r, uint32_t addr) {
    asm volatile("ldmatrix.sync.aligned.m8n8.x2.shared.b16 {%0,%1}, [%2];"
        : "=r"(r[0]), "=r"(r[1]) : "r"(addr));
}

#define CPA(dst, src, sz) \
    asm volatile("cp.async.cg.shared.global [%0], [%1], 16, %2;" \
                 :: "r"(dst), "l"(src), "r"(sz))

template<bool GI>
__global__ __launch_bounds__(256) void mma_f16x3_a(
    const uint32_t* __restrict__ A, const uint32_t* __restrict__ A2,
    const uint32_t* __restrict__ B, float* __restrict__ C,
    int M, int Nout, int K)
{
    extern __shared__ uint32_t smp[];
    uint32_t smemBase = (uint32_t)__cvta_generic_to_shared(smp);

    int bm = blockIdx.x, bn = blockIdx.y;
    int tid = threadIdx.x;
    int lane = tid & 31;
    int warp = tid >> 5;
    int wm = warp >> 2;
    int wn = warp & 3;
    int mb = wm * 64;
    int nb = wn * 32;

    int lrow = tid >> 1;       // 0..127
    int h    = tid & 1;        // which 32B half of the 64B row-chunk
    int aRow = bm * 128 + lrow;
    int bRow = bn * 128 + lrow;
    bool aOk = aRow < M;
    int aRowC = aOk ? aRow : (M - 1);
    uint32_t szA = aOk ? 16u : 0u;
    uint32_t szB = 16u;

    const uint32_t* aH  = A + (size_t)aRowC * H + 8 * h;
    const uint32_t* a2H = GI ? (A2 + (size_t)aRowC * H + 8 * h) : nullptr;
    const uint32_t* bH  = B + (size_t)bRow * K + 8 * h;
    int halfB = K >> 1;
    uint32_t dstRow = (uint32_t)(lrow * 80 + h * 32);

    // ldmatrix lane-address components (within a stage)
    int l15 = lane & 15;
    uint32_t aAddrOff = (uint32_t)((mb + l15) * 80 + (lane >> 4) * 16);
    uint32_t bAddrOff = (uint32_t)(B_H_OFF + (nb + (l15 & 7)) * 80 + ((l15 >> 3) * 16));

    float acc[4][4][4];
    #pragma unroll
    for (int i = 0; i < 4; i++)
        #pragma unroll
        for (int j = 0; j < 4; j++)
            #pragma unroll
            for (int c = 0; c < 4; c++) acc[i][j][c] = 0.f;

    int nChunks = K >> 5;   // BK=32

#define ISSUE(c, stg) do { \
        int _cc = GI ? ((c) & 3) : (c); \
        const uint32_t* _sa = (GI && (c) >= 4) ? (a2H + 16 * _cc) : (aH + 16 * _cc); \
        uint32_t _d = smemBase + (uint32_t)(stg) * STG_BYTES + dstRow; \
        CPA(_d,                    _sa,          szA); \
        CPA(_d + 16u,              _sa + 4,      szA); \
        CPA(_d + A_L_OFF,          _sa + 64,     szA); \
        CPA(_d + A_L_OFF + 16u,    _sa + 68,     szA); \
        const uint32_t* _sb = bH + 16 * (c); \
        CPA(_d + B_H_OFF,          _sb,          szB); \
        CPA(_d + B_H_OFF + 16u,    _sb + 4,      szB); \
        CPA(_d + B_L_OFF,          _sb + halfB,      szB); \
        CPA(_d + B_L_OFF + 16u,    _sb + halfB + 4,  szB); \
        asm volatile("cp.async.commit_group;" ::: "memory"); \
    } while (0)

    ISSUE(0, 0);
    if (nChunks > 1) ISSUE(1, 1);

    for (int c = 0; c < nChunks; c++) {
        if (c + 1 < nChunks)
            asm volatile("cp.async.wait_group 1;" ::: "memory");
        else
            asm volatile("cp.async.wait_group 0;" ::: "memory");
        __syncthreads();

        if (c + 2 < nChunks) ISSUE(c + 2, (c + 2) % 3);

        uint32_t sb = smemBase + (uint32_t)(c % 3) * STG_BYTES;
        #pragma unroll
        for (int s = 0; s < 2; s++) {
            uint32_t ko = (uint32_t)(s * 32);
            uint32_t afH[4][4], afL[4][4];
            #pragma unroll
            for (int i = 0; i < 4; i++) {
                uint32_t ad = sb + aAddrOff + (uint32_t)(i * 16 * 80) + ko;
                ldsm_x4(afH[i], ad);
                ldsm_x4(afL[i], ad + A_L_OFF);
            }
            uint32_t bfH[4][2], bfL[4][2];
            #pragma unroll
            for (int j = 0; j < 4; j++) {
                uint32_t bd = sb + bAddrOff + (uint32_t)(j * 8 * 80) + ko;
                ldsm_x2(bfH[j], bd);
                ldsm_x2(bfL[j], bd + A_L_OFF);
            }
            #pragma unroll
            for (int i = 0; i < 4; i++)
                #pragma unroll
                for (int j = 0; j < 4; j++) {
                    mma_f16(acc[i][j], afL[i], bfH[j]);
                    mma_f16(acc[i][j], afH[i], bfL[j]);
                    mma_f16(acc[i][j], afH[i], bfH[j]);
                }
        }
    }
#undef ISSUE

    int qm = lane >> 2;
    #pragma unroll
    for (int i = 0; i < 4; i++) {
        int r0 = bm * 128 + mb + i * 16 + qm;
        int r1 = r0 + 8;
        #pragma unroll
        for (int j = 0; j < 4; j++) {
            int col = bn * 128 + nb + j * 8 + (lane & 3) * 2;
            if (r0 < M)
                *(float2*)(C + (size_t)r0 * Nout + col) = make_float2(acc[i][j][0], acc[i][j][1]);
            if (r1 < M)
                *(float2*)(C + (size_t)r1 * Nout + col) = make_float2(acc[i][j][2], acc[i][j][3]);
        }
    }
}

// ---------------- fused GRU elementwise (float4) + de-interleaved split writes ----
__global__ void gru_kernel(const float* __restrict__ hv,
                           const float* __restrict__ b_ih, const float* __restrict__ b_hh,
                           const float* __restrict__ u1, const float* __restrict__ u2,
                           float* __restrict__ out, int writeSplit, int N)
{
    int idx = blockIdx.x * blockDim.x + threadIdx.x;
    if (idx >= N * 32) return;
    int n = idx >> 5, q = idx & 31;
    float d = g_deg[n], s = g_se[n];
    const float4* GI4 = (const float4*)(g_gi + (size_t)n * H3);
    const float4* GH4 = (const float4*)(g_gh + (size_t)n * H3);
    const float4* U1 = (const float4*)u1;
    const float4* U2 = (const float4*)u2;
    const float4* BI = (const float4*)b_ih;
    const float4* BH = (const float4*)b_hh;

    float4 hvv = ((const float4*)(hv + (size_t)n * H))[q];
    float4 ir4 = GI4[q], iz4 = GI4[q + 32], in4 = GI4[q + 64];
    float4 hr4 = GH4[q], hz4 = GH4[q + 32], hn4 = GH4[q + 64];
    float4 u1r = U1[q],  u1z = U1[q + 32],  u1n = U1[q + 64];
    float4 u2r = U2[q],  u2z = U2[q + 32],  u2n = U2[q + 64];
    float4 bir = BI[q],  biz = BI[q + 32],  bin_ = BI[q + 64];
    float4 bhr = BH[q],  bhz = BH[q + 32],  bhn = BH[q + 64];

    float4 o;
    #pragma unroll
    for (int c = 0; c < 4; c++) {
        float ir = (&ir4.x)[c] + s * (&u1r.x)[c] + d * (&u2r.x)[c] + (&bir.x)[c];
        float iz = (&iz4.x)[c] + s * (&u1z.x)[c] + d * (&u2z.x)[c] + (&biz.x)[c];
        float in_ = (&in4.x)[c] + s * (&u1n.x)[c] + d * (&u2n.x)[c] + (&bin_.x)[c];
        float hr = (&hr4.x)[c] + (&bhr.x)[c];
        float hz = (&hz4.x)[c] + (&bhz.x)[c];
        float hn = (&hn4.x)[c] + (&bhn.x)[c];
        float r = 1.f / (1.f + expf(-(ir + hr)));
        float z = 1.f / (1.f + expf(-(iz + hz)));
        float nn = tanhf(in_ + r * hn);
        (&o.x)[c] = (1.f - z) * nn + z * (&hvv.x)[c];
    }
    ((float4*)(out + (size_t)n * H))[q] = o;

    if (writeSplit) {
        uint32_t h0, l0, h1, l1;
        uint32_t* rp = g_hvP + (size_t)n * H;
        split_h2(o.x, o.y, h0, l0);
        split_h2(o.z, o.w, h1, l1);
        ((uint2*)rp)[q] = make_uint2(h0, h1);
        ((uint2*)(rp + 64))[q] = make_uint2(l0, l1);
        rp = g_dhvP + (size_t)n * H;
        split_h2(d * o.x, d * o.y, h0, l0);
        split_h2(d * o.z, d * o.w, h1, l1);
        ((uint2*)rp)[q] = make_uint2(h0, h1);
        ((uint2*)(rp + 64))[q] = make_uint2(l0, l1);
    }
}

// ---------------- launch ----------------
extern "C" void kernel_launch(void* const* d_in, const int* in_sizes, int n_in,
                              void* d_out, int out_size)
{
    const float* hv0   = (const float*)d_in[0];
    const float* he    = (const float*)d_in[1];
    const int*   src   = (const int*)d_in[2];
    const int*   dst   = (const int*)d_in[3];
    const float* W_msg = (const float*)d_in[4];
    const float* b_msg = (const float*)d_in[5];
    const float* W_ih  = (const float*)d_in[6];
    const float* W_hh  = (const float*)d_in[7];
    const float* b_ih  = (const float*)d_in[8];
    const float* b_hh  = (const float*)d_in[9];

    int N = in_sizes[0] / H;
    int E = in_sizes[2];
    int T = in_sizes[8] / H3;
    if (T > MAXT) T = MAXT;

    static cudaStream_t s2 = nullptr;
    static cudaEvent_t evStart = nullptr, evFold = nullptr, evSplit0 = nullptr,
                       evGh = nullptr, evGru = nullptr;
    if (!s2) {
        cudaStreamCreateWithFlags(&s2, cudaStreamNonBlocking);
        cudaEventCreateWithFlags(&evStart,  cudaEventDisableTiming);
        cudaEventCreateWithFlags(&evFold,   cudaEventDisableTiming);
        cudaEventCreateWithFlags(&evSplit0, cudaEventDisableTiming);
        cudaEventCreateWithFlags(&evGh,     cudaEventDisableTiming);
        cudaEventCreateWithFlags(&evGru,    cudaEventDisableTiming);
        cudaFuncSetAttribute(mma_f16x3_a<true>,
                             cudaFuncAttributeMaxDynamicSharedMemorySize, GEMM_SMEM);
        cudaFuncSetAttribute(mma_f16x3_a<false>,
                             cudaFuncAttributeMaxDynamicSharedMemorySize, GEMM_SMEM);
    }

    uint32_t *phvP, *pdhvP, *pSP, *pWcP, *pWhhP;
    float *pgi, *pgh, *ph0, *ph1, *pdeg, *pse, *pu1, *pu2;
    cudaGetSymbolAddress((void**)&phvP,  g_hvP);
    cudaGetSymbolAddress((void**)&pdhvP, g_dhvP);
    cudaGetSymbolAddress((void**)&pSP,   g_SP);
    cudaGetSymbolAddress((void**)&pWcP,  g_WcP);
    cudaGetSymbolAddress((void**)&pWhhP, g_WhhP);
    cudaGetSymbolAddress((void**)&pgi,  g_gi);
    cudaGetSymbolAddress((void**)&pgh,  g_gh);
    cudaGetSymbolAddress((void**)&ph0,  g_h0);
    cudaGetSymbolAddress((void**)&ph1,  g_h1);
    cudaGetSymbolAddress((void**)&pdeg, g_deg);
    cudaGetSymbolAddress((void**)&pse,  g_se);
    cudaGetSymbolAddress((void**)&pu1,  g_u1);
    cudaGetSymbolAddress((void**)&pu2,  g_u2);

    int nb = (N + 1023) / 1024;

    // fork: s2 = weight folds + packing; main = CSR build + split0
    cudaEventRecord(evStart, 0);
    cudaStreamWaitEvent(s2, evStart, 0);

    long wc_total = (long)T * H3 * H2;
    fold_wc_kernel<<<(int)((wc_total + 255) / 256), 256, 0, s2>>>(W_ih, W_msg, T);
    int packTot = T * H3 * 128 + T * H3 * 64;
    pack_w_kernel<<<(packTot + 255) / 256, 256, 0, s2>>>(W_hh, T);
    fold_u_kernel<<<(T * H3 + 255) / 256, 256, 0, s2>>>(W_ih, W_msg, b_msg, T);
    cudaEventRecord(evFold, s2);

    zero2_kernel<<<128, 256>>>(pdeg, pse, N);
    degse_kernel<<<(E + 255) / 256, 256>>>(dst, he, E);
    scan1_kernel<<<nb, 1024>>>(N);
    scan2_kernel<<<1, 32>>>(nb);
    scan3_kernel<<<nb, 1024>>>(N, E);
    fill_kernel<<<(E + 255) / 256, 256>>>(src, dst, E);
    split0_kernel<<<(N * 32 + 255) / 256, 256>>>(hv0, N);
    cudaEventRecord(evSplit0, 0);

    const float* cur = hv0;
    dim3 g1((N + 127) / 128, 3);
    for (int t = 0; t < T; t++) {
        // main: gather (fp32 reads) -> gi GEMM ([dhv | S] @ Wc^T, K=256, packed)
        gather_kernel<<<(N * 32 + 255) / 256, 256>>>(cur, N);
        if (t == 0) cudaStreamWaitEvent(0, evFold, 0);
        mma_f16x3_a<true><<<g1, 256, GEMM_SMEM>>>(pdhvP, pSP, pWcP + (size_t)t * H3 * H2,
                                                  pgi, N, H3, H2);

        // s2: gh GEMM (hvP @ WhhP^T, K=128)
        cudaStreamWaitEvent(s2, (t == 0) ? evSplit0 : evGru, 0);
        mma_f16x3_a<false><<<g1, 256, GEMM_SMEM, s2>>>(phvP, nullptr,
                                                       pWhhP + (size_t)t * H3 * H,
                                                       pgh, N, H3, H);
        cudaEventRecord(evGh, s2);

        // join -> GRU on main
        cudaStreamWaitEvent(0, evGh, 0);
        float* outp = (t == T - 1) ? (float*)d_out : ((t & 1) ? ph1 : ph0);
        gru_kernel<<<(N * 32 + 255) / 256, 256>>>(cur, b_ih + (size_t)t * H3, b_hh + (size_t)t * H3,
                                                  pu1 + (size_t)t * H3, pu2 + (size_t)t * H3,
                                                  outp, (t < T - 1) ? 1 : 0, N);
        cudaEventRecord(evGru, 0);
        cur = outp;
    }
}

// round 17
// speedup vs baseline: 1.0909x; 1.0909x over previous
#include <cuda_runtime.h>
#include <cuda_fp16.h>
#include <math.h>
#include <stdint.h>

#define H   128
#define H2  256
#define H3  384
#define WMC 257          // W_msg columns = 2H+1

#define MAXN 50000
#define MAXE 800000
#define MAXT 4
#define MAXNB ((MAXN + 1023) / 1024)

// ---------------- scratch (static device globals; no allocation) ----------------
// Packed fp16 hi/lo, DE-INTERLEAVED per row: [64 H-words | 64 L-words]
__device__ uint32_t g_hvP [(size_t)MAXN * H];   // hv packed
__device__ uint32_t g_dhvP[(size_t)MAXN * H];   // deg*hv packed
__device__ uint32_t g_SP  [(size_t)MAXN * H];   // gathered S packed
__device__ float    g_gi  [(size_t)MAXN * H3];
__device__ float    g_gh  [(size_t)MAXN * H3];
__device__ float    g_h0  [(size_t)MAXN * H];
__device__ float    g_h1  [(size_t)MAXN * H];
__device__ float    g_deg [MAXN];
__device__ float    g_se  [MAXN];
__device__ float    g_Wc  [(size_t)MAXT * H3 * H2];  // fold intermediate (fp32)
__device__ uint32_t g_WcP [(size_t)MAXT * H3 * H2];  // Wc packed (row: 128 H + 128 L)
__device__ uint32_t g_WhhP[(size_t)MAXT * H3 * H];   // W_hh packed (row: 64 H + 64 L)
__device__ float    g_u1  [MAXT * H3];
__device__ float    g_u2  [MAXT * H3];
__device__ int      g_off [MAXN + 1];
__device__ int      g_cur [MAXN];
__device__ int      g_csrc[MAXE];
__device__ int      g_bsum[MAXNB];
__device__ int      g_bpre[MAXNB];

__device__ __forceinline__ void split_h2(float x, float y, uint32_t& hi, uint32_t& lo) {
    __half hx = __float2half_rn(x);
    __half hy = __float2half_rn(y);
    __half lx = __float2half_rn(x - __half2float(hx));
    __half ly = __float2half_rn(y - __half2float(hy));
    __half2 h = __halves2half2(hx, hy);
    __half2 l = __halves2half2(lx, ly);
    hi = *(uint32_t*)&h;
    lo = *(uint32_t*)&l;
}

// ---------------- utility ----------------
__global__ void zero2_kernel(float* __restrict__ p, float* __restrict__ q, int n) {
    int i = blockIdx.x * blockDim.x + threadIdx.x;
    int stride = gridDim.x * blockDim.x;
    for (int k = i; k < n; k += stride) { p[k] = 0.f; q[k] = 0.f; }
}

__global__ void degse_kernel(const int* __restrict__ dst, const float* __restrict__ he, int E) {
    int e = blockIdx.x * blockDim.x + threadIdx.x;
    if (e >= E) return;
    int d = dst[e];
    atomicAdd(&g_deg[d], 1.0f);
    atomicAdd(&g_se[d], he[e]);
}

// ---------------- CSR prefix scan: multi-block ----------------
__global__ void scan1_kernel(int N) {
    __shared__ int wsum[32];
    int i = blockIdx.x * 1024 + threadIdx.x;
    int lane = threadIdx.x & 31, wid = threadIdx.x >> 5;
    int v = (i < N) ? (int)g_deg[i] : 0;
    int x = v;
    #pragma unroll
    for (int o = 1; o < 32; o <<= 1) {
        int t = __shfl_up_sync(0xFFFFFFFFu, x, o);
        if (lane >= o) x += t;
    }
    if (lane == 31) wsum[wid] = x;
    __syncthreads();
    if (wid == 0) {
        int s = wsum[lane];
        #pragma unroll
        for (int o = 1; o < 32; o <<= 1) {
            int t = __shfl_up_sync(0xFFFFFFFFu, s, o);
            if (lane >= o) s += t;
        }
        wsum[lane] = s;
    }
    __syncthreads();
    int wpre = (wid == 0) ? 0 : wsum[wid - 1];
    if (i < N) g_off[i] = wpre + x - v;
    if (threadIdx.x == 1023) g_bsum[blockIdx.x] = wpre + x;
}

__global__ void scan2_kernel(int nb) {
    if (threadIdx.x == 0) {
        int s = 0;
        for (int b = 0; b < nb; b++) { int t = g_bsum[b]; g_bpre[b] = s; s += t; }
    }
}

__global__ void scan3_kernel(int N, int E) {
    int i = blockIdx.x * 1024 + threadIdx.x;
    if (i < N) {
        int o = g_off[i] + g_bpre[blockIdx.x];
        g_off[i] = o;
        g_cur[i] = o;
    }
    if (i == 0) g_off[N] = E;
}

__global__ void fill_kernel(const int* __restrict__ src, const int* __restrict__ dst, int E) {
    int e = blockIdx.x * blockDim.x + threadIdx.x;
    if (e >= E) return;
    int pos = atomicAdd(&g_cur[dst[e]], 1);
    g_csrc[pos] = src[e];
}

// ---------------- weight folding + packing ----------------
__global__ void fold_wc_kernel(const float* __restrict__ W_ih, const float* __restrict__ W_msg, int T) {
    long idx = (long)blockIdx.x * blockDim.x + threadIdx.x;
    if (idx >= (long)T * H3 * H2) return;
    int k = (int)(idx % H2);
    int j = (int)((idx / H2) % H3);
    int t = (int)(idx / ((long)H2 * H3));
    const float* wi = W_ih + ((size_t)t * H3 + j) * H2;
    const float* wm = W_msg + (size_t)t * H2 * WMC + k;
    float a0 = 0.f, a1 = 0.f, a2 = 0.f, a3 = 0.f;
    #pragma unroll 2
    for (int i = 0; i < H2; i += 4) {
        a0 += __ldg(wi + i)     * __ldg(wm + (size_t)(i)     * WMC);
        a1 += __ldg(wi + i + 1) * __ldg(wm + (size_t)(i + 1) * WMC);
        a2 += __ldg(wi + i + 2) * __ldg(wm + (size_t)(i + 2) * WMC);
        a3 += __ldg(wi + i + 3) * __ldg(wm + (size_t)(i + 3) * WMC);
    }
    g_Wc[idx] = (a0 + a1) + (a2 + a3);
}

// pack weights de-interleaved: Wc rows (128 pairs), Whh rows (64 pairs)
__global__ void pack_w_kernel(const float* __restrict__ W_hh, int T) {
    int i = blockIdx.x * blockDim.x + threadIdx.x;
    int totWc = T * H3 * 128;
    int totWh = T * H3 * 64;
    if (i < totWc) {
        int p = i % 128;
        int row = i / 128;
        float2 v = ((const float2*)g_Wc)[(size_t)row * 128 + p];
        uint32_t h, l;
        split_h2(v.x, v.y, h, l);
        uint32_t* rp = g_WcP + (size_t)row * H2;
        rp[p] = h;
        rp[128 + p] = l;
    } else if (i < totWc + totWh) {
        int j = i - totWc;
        int p = j % 64;
        int row = j / 64;
        float2 v = ((const float2*)W_hh)[(size_t)row * 64 + p];
        uint32_t h, l;
        split_h2(v.x, v.y, h, l);
        uint32_t* rp = g_WhhP + (size_t)row * H;
        rp[p] = h;
        rp[64 + p] = l;
    }
}

__global__ void fold_u_kernel(const float* __restrict__ W_ih, const float* __restrict__ W_msg,
                              const float* __restrict__ b_msg, int T) {
    int idx = blockIdx.x * blockDim.x + threadIdx.x;
    if (idx >= T * H3) return;
    int j = idx % H3, t = idx / H3;
    const float* wi = W_ih + ((size_t)t * H3 + j) * H2;
    const float* wm = W_msg + (size_t)t * H2 * WMC;
    const float* bm = b_msg + (size_t)t * H2;
    float a1 = 0.f, a2 = 0.f;
    for (int i = 0; i < H2; i++) {
        float w = wi[i];
        a1 += w * wm[(size_t)i * WMC + H2];
        a2 += w * bm[i];
    }
    g_u1[idx] = a1;
    g_u2[idx] = a2;
}

// ---------------- split initial hv (and deg*hv), de-interleaved ----------------
__global__ void split0_kernel(const float* __restrict__ hv, int N) {
    int idx = blockIdx.x * blockDim.x + threadIdx.x;
    if (idx >= N * 32) return;
    int n = idx >> 5, q = idx & 31;
    float4 v = ((const float4*)(hv + (size_t)n * H))[q];
    float d = g_deg[n];
    uint32_t h0, l0, h1, l1;
    uint32_t* rp = g_hvP + (size_t)n * H;
    split_h2(v.x, v.y, h0, l0);
    split_h2(v.z, v.w, h1, l1);
    ((uint2*)rp)[q] = make_uint2(h0, h1);
    ((uint2*)(rp + 64))[q] = make_uint2(l0, l1);
    rp = g_dhvP + (size_t)n * H;
    split_h2(d * v.x, d * v.y, h0, l0);
    split_h2(d * v.z, d * v.w, h1, l1);
    ((uint2*)rp)[q] = make_uint2(h0, h1);
    ((uint2*)(rp + 64))[q] = make_uint2(l0, l1);
}

// ---------------- gather: S[n] = sum hv[csrc[e]] (fp32 reads), packed write -------
__global__ void gather_kernel(const float* __restrict__ hv, int N) {
    int n = (blockIdx.x * blockDim.x + threadIdx.x) >> 5;
    int lane = threadIdx.x & 31;
    if (n >= N) return;
    int beg = g_off[n], end = g_off[n + 1];
    float4 acc0 = make_float4(0.f, 0.f, 0.f, 0.f);
    float4 acc1 = make_float4(0.f, 0.f, 0.f, 0.f);
    float4 acc2 = make_float4(0.f, 0.f, 0.f, 0.f);
    float4 acc3 = make_float4(0.f, 0.f, 0.f, 0.f);
    int e = beg;
    for (; e + 4 <= end; e += 4) {
        int s0 = __ldg(g_csrc + e);
        int s1 = __ldg(g_csrc + e + 1);
        int s2 = __ldg(g_csrc + e + 2);
        int s3 = __ldg(g_csrc + e + 3);
        float4 v0 = *(((const float4*)(hv + (size_t)s0 * H)) + lane);
        float4 v1 = *(((const float4*)(hv + (size_t)s1 * H)) + lane);
        float4 v2 = *(((const float4*)(hv + (size_t)s2 * H)) + lane);
        float4 v3 = *(((const float4*)(hv + (size_t)s3 * H)) + lane);
        acc0.x += v0.x; acc0.y += v0.y; acc0.z += v0.z; acc0.w += v0.w;
        acc1.x += v1.x; acc1.y += v1.y; acc1.z += v1.z; acc1.w += v1.w;
        acc2.x += v2.x; acc2.y += v2.y; acc2.z += v2.z; acc2.w += v2.w;
        acc3.x += v3.x; acc3.y += v3.y; acc3.z += v3.z; acc3.w += v3.w;
    }
    for (; e < end; e++) {
        int s0 = __ldg(g_csrc + e);
        float4 v0 = *(((const float4*)(hv + (size_t)s0 * H)) + lane);
        acc0.x += v0.x; acc0.y += v0.y; acc0.z += v0.z; acc0.w += v0.w;
    }
    acc0.x += acc1.x; acc0.y += acc1.y; acc0.z += acc1.z; acc0.w += acc1.w;
    acc2.x += acc3.x; acc2.y += acc3.y; acc2.z += acc3.z; acc2.w += acc3.w;
    acc0.x += acc2.x; acc0.y += acc2.y; acc0.z += acc2.z; acc0.w += acc2.w;
    uint32_t h0, l0, h1, l1;
    split_h2(acc0.x, acc0.y, h0, l0);
    split_h2(acc0.z, acc0.w, h1, l1);
    uint32_t* rp = g_SP + (size_t)n * H;
    ((uint2*)rp)[lane] = make_uint2(h0, h1);
    ((uint2*)(rp + 64))[lane] = make_uint2(l0, l1);
}

// ---------------- 3xFP16 GEMM (NT), cp.async 3-stage + ldmatrix, multi-tile CTA ----
// Each CTA processes up to 4 M-tiles (same bn) in one flat chunk pipeline:
// one pipeline fill per CTA; tile epilogues overlap next tile's loads.
#define STG_BYTES 24576u
#define GEMM_SMEM (3 * 24576)
#define TM 4

__device__ __forceinline__ void mma_f16(float* acc, const uint32_t* a, const uint32_t* b) {
    asm volatile(
        "mma.sync.aligned.m16n8k16.row.col.f32.f16.f16.f32 "
        "{%0,%1,%2,%3}, {%4,%5,%6,%7}, {%8,%9}, {%0,%1,%2,%3};"
        : "+f"(acc[0]), "+f"(acc[1]), "+f"(acc[2]), "+f"(acc[3])
        : "r"(a[0]), "r"(a[1]), "r"(a[2]), "r"(a[3]), "r"(b[0]), "r"(b[1]));
}

__device__ __forceinline__ void ldsm_x4(uint32_t* r, uint32_t addr) {
    asm volatile("ldmatrix.sync.aligned.m8n8.x4.shared.b16 {%0,%1,%2,%3}, [%4];"
        : "=r"(r[0]), "=r"(r[1]), "=r"(r[2]), "=r"(r[3]) : "r"(addr));
}
__device__ __forceinline__ void ldsm_x2(uint32_t* r, uint32_t addr) {
    asm volatile("ldmatrix.sync.aligned.m8n8.x2.shared.b16 {%0,%1}, [%2];"
        : "=r"(r[0]), "=r"(r[1]) : "r"(addr));
}

#define CPA(dst, src, sz) \
    asm volatile("cp.async.cg.shared.global [%0], [%1], 16, %2;" \
                 :: "r"(dst), "l"(src), "r"(sz))

template<bool GI>
__global__ __launch_bounds__(256) void mma_f16x3_a(
    const uint32_t* __restrict__ A, const uint32_t* __restrict__ A2,
    const uint32_t* __restrict__ B, float* __restrict__ C,
    int M, int Nout, int K)
{
    extern __shared__ uint32_t smp[];
    uint32_t smemBase = (uint32_t)__cvta_generic_to_shared(smp);

    constexpr int SHIFT = GI ? 4 : 3;       // nChunks = 16 (K=256) or 8 (K=128)
    constexpr int NCH = 1 << SHIFT;

    int bm = blockIdx.x, bn = blockIdx.y;
    int tid = threadIdx.x;
    int lane = tid & 31;
    int warp = tid >> 5;
    int wm = warp >> 2;
    int wn = warp & 3;
    int mb = wm * 64;
    int nb = wn * 32;

    int lrow = tid >> 1;
    int h    = tid & 1;
    int bRow = bn * 128 + lrow;
    const uint32_t* bH = B + (size_t)bRow * K + 4 * h;
    int halfB = K >> 1;
    uint32_t dstRow = (uint32_t)(lrow * 48 + h * 16);

    // ldmatrix lane-address components (within a stage)
    int l15 = lane & 15;
    uint32_t aAddrOff = (uint32_t)((mb + l15) * 48 + (lane >> 4) * 16);
    uint32_t bAddrOff = (uint32_t)(12288 + (nb + (l15 & 7)) * 48 + ((l15 >> 3) * 16));

    int nTilesM = (M + 127) >> 7;
    int tiles = nTilesM - bm * TM;
    if (tiles <= 0) return;
    if (tiles > TM) tiles = TM;
    int total = tiles << SHIFT;

    float acc[4][4][4];
    #pragma unroll
    for (int i = 0; i < 4; i++)
        #pragma unroll
        for (int j = 0; j < 4; j++)
            #pragma unroll
            for (int c = 0; c < 4; c++) acc[i][j][c] = 0.f;

#define ISSUE(g, stg) do { \
        int _t = (g) >> SHIFT; \
        int _c = (g) & (NCH - 1); \
        int _arow = (bm * TM + _t) * 128 + lrow; \
        bool _ok = _arow < M; \
        uint32_t _sz = _ok ? 16u : 0u; \
        int _cc = GI ? (_c & 7) : _c; \
        const uint32_t* _base = (GI && _c >= 8) ? A2 : A; \
        const uint32_t* _sa = _base + (size_t)(_ok ? _arow : 0) * H + 4 * h + 8 * _cc; \
        uint32_t _d = smemBase + (uint32_t)(stg) * STG_BYTES + dstRow; \
        CPA(_d,          _sa,          _sz); \
        CPA(_d + 6144u,  _sa + 64,     _sz); \
        const uint32_t* _sb = bH + 8 * _c; \
        CPA(_d + 12288u, _sb,          16u); \
        CPA(_d + 18432u, _sb + halfB,  16u); \
        asm volatile("cp.async.commit_group;" ::: "memory"); \
    } while (0)

    ISSUE(0, 0);
    if (total > 1) ISSUE(1, 1);

    for (int g = 0; g < total; g++) {
        if (g + 1 < total)
            asm volatile("cp.async.wait_group 1;" ::: "memory");
        else
            asm volatile("cp.async.wait_group 0;" ::: "memory");
        __syncthreads();

        if (g + 2 < total) ISSUE(g + 2, (g + 2) % 3);

        uint32_t sb = smemBase + (uint32_t)(g % 3) * STG_BYTES;
        uint32_t afH[4][4], afL[4][4];
        #pragma unroll
        for (int i = 0; i < 4; i++) {
            uint32_t ad = sb + aAddrOff + (uint32_t)(i * 16 * 48);
            ldsm_x4(afH[i], ad);
            ldsm_x4(afL[i], ad + 6144u);
        }
        uint32_t bfH[4][2], bfL[4][2];
        #pragma unroll
        for (int j = 0; j < 4; j++) {
            uint32_t bd = sb + bAddrOff + (uint32_t)(j * 8 * 48);
            ldsm_x2(bfH[j], bd);
            ldsm_x2(bfL[j], bd + 6144u);
        }
        #pragma unroll
        for (int i = 0; i < 4; i++)
            #pragma unroll
            for (int j = 0; j < 4; j++) {
                mma_f16(acc[i][j], afL[i], bfH[j]);
                mma_f16(acc[i][j], afH[i], bfL[j]);
                mma_f16(acc[i][j], afH[i], bfH[j]);
            }

        if ((g & (NCH - 1)) == NCH - 1) {
            // tile epilogue (register -> global; overlaps next tile's in-flight loads)
            int tile = g >> SHIFT;
            int m0 = (bm * TM + tile) * 128;
            int qm = lane >> 2;
            #pragma unroll
            for (int i = 0; i < 4; i++) {
                int r0 = m0 + mb + i * 16 + qm;
                int r1 = r0 + 8;
                #pragma unroll
                for (int j = 0; j < 4; j++) {
                    int col = bn * 128 + nb + j * 8 + (lane & 3) * 2;
                    if (r0 < M)
                        *(float2*)(C + (size_t)r0 * Nout + col) = make_float2(acc[i][j][0], acc[i][j][1]);
                    if (r1 < M)
                        *(float2*)(C + (size_t)r1 * Nout + col) = make_float2(acc[i][j][2], acc[i][j][3]);
                    acc[i][j][0] = 0.f; acc[i][j][1] = 0.f;
                    acc[i][j][2] = 0.f; acc[i][j][3] = 0.f;
                }
            }
        }
    }
#undef ISSUE
}

// ---------------- fused GRU elementwise (float4) + de-interleaved split writes ----
__global__ void gru_kernel(const float* __restrict__ hv,
                           const float* __restrict__ b_ih, const float* __restrict__ b_hh,
                           const float* __restrict__ u1, const float* __restrict__ u2,
                           float* __restrict__ out, int writeSplit, int N)
{
    int idx = blockIdx.x * blockDim.x + threadIdx.x;
    if (idx >= N * 32) return;
    int n = idx >> 5, q = idx & 31;
    float d = g_deg[n], s = g_se[n];
    const float4* GI4 = (const float4*)(g_gi + (size_t)n * H3);
    const float4* GH4 = (const float4*)(g_gh + (size_t)n * H3);
    const float4* U1 = (const float4*)u1;
    const float4* U2 = (const float4*)u2;
    const float4* BI = (const float4*)b_ih;
    const float4* BH = (const float4*)b_hh;

    float4 hvv = ((const float4*)(hv + (size_t)n * H))[q];
    float4 ir4 = GI4[q], iz4 = GI4[q + 32], in4 = GI4[q + 64];
    float4 hr4 = GH4[q], hz4 = GH4[q + 32], hn4 = GH4[q + 64];
    float4 u1r = U1[q],  u1z = U1[q + 32],  u1n = U1[q + 64];
    float4 u2r = U2[q],  u2z = U2[q + 32],  u2n = U2[q + 64];
    float4 bir = BI[q],  biz = BI[q + 32],  bin_ = BI[q + 64];
    float4 bhr = BH[q],  bhz = BH[q + 32],  bhn = BH[q + 64];

    float4 o;
    #pragma unroll
    for (int c = 0; c < 4; c++) {
        float ir = (&ir4.x)[c] + s * (&u1r.x)[c] + d * (&u2r.x)[c] + (&bir.x)[c];
        float iz = (&iz4.x)[c] + s * (&u1z.x)[c] + d * (&u2z.x)[c] + (&biz.x)[c];
        float in_ = (&in4.x)[c] + s * (&u1n.x)[c] + d * (&u2n.x)[c] + (&bin_.x)[c];
        float hr = (&hr4.x)[c] + (&bhr.x)[c];
        float hz = (&hz4.x)[c] + (&bhz.x)[c];
        float hn = (&hn4.x)[c] + (&bhn.x)[c];
        float r = 1.f / (1.f + expf(-(ir + hr)));
        float z = 1.f / (1.f + expf(-(iz + hz)));
        float nn = tanhf(in_ + r * hn);
        (&o.x)[c] = (1.f - z) * nn + z * (&hvv.x)[c];
    }
    ((float4*)(out + (size_t)n * H))[q] = o;

    if (writeSplit) {
        uint32_t h0, l0, h1, l1;
        uint32_t* rp = g_hvP + (size_t)n * H;
        split_h2(o.x, o.y, h0, l0);
        split_h2(o.z, o.w, h1, l1);
        ((uint2*)rp)[q] = make_uint2(h0, h1);
        ((uint2*)(rp + 64))[q] = make_uint2(l0, l1);
        rp = g_dhvP + (size_t)n * H;
        split_h2(d * o.x, d * o.y, h0, l0);
        split_h2(d * o.z, d * o.w, h1, l1);
        ((uint2*)rp)[q] = make_uint2(h0, h1);
        ((uint2*)(rp + 64))[q] = make_uint2(l0, l1);
    }
}

// ---------------- launch ----------------
extern "C" void kernel_launch(void* const* d_in, const int* in_sizes, int n_in,
                              void* d_out, int out_size)
{
    const float* hv0   = (const float*)d_in[0];
    const float* he    = (const float*)d_in[1];
    const int*   src   = (const int*)d_in[2];
    const int*   dst   = (const int*)d_in[3];
    const float* W_msg = (const float*)d_in[4];
    const float* b_msg = (const float*)d_in[5];
    const float* W_ih  = (const float*)d_in[6];
    const float* W_hh  = (const float*)d_in[7];
    const float* b_ih  = (const float*)d_in[8];
    const float* b_hh  = (const float*)d_in[9];

    int N = in_sizes[0] / H;
    int E = in_sizes[2];
    int T = in_sizes[8] / H3;
    if (T > MAXT) T = MAXT;

    static cudaStream_t s2 = nullptr;
    static cudaEvent_t evStart = nullptr, evFold = nullptr, evSplit0 = nullptr,
                       evGh = nullptr, evGru = nullptr;
    if (!s2) {
        cudaStreamCreateWithFlags(&s2, cudaStreamNonBlocking);
        cudaEventCreateWithFlags(&evStart,  cudaEventDisableTiming);
        cudaEventCreateWithFlags(&evFold,   cudaEventDisableTiming);
        cudaEventCreateWithFlags(&evSplit0, cudaEventDisableTiming);
        cudaEventCreateWithFlags(&evGh,     cudaEventDisableTiming);
        cudaEventCreateWithFlags(&evGru,    cudaEventDisableTiming);
        cudaFuncSetAttribute(mma_f16x3_a<true>,
                             cudaFuncAttributeMaxDynamicSharedMemorySize, GEMM_SMEM);
        cudaFuncSetAttribute(mma_f16x3_a<false>,
                             cudaFuncAttributeMaxDynamicSharedMemorySize, GEMM_SMEM);
    }

    uint32_t *phvP, *pdhvP, *pSP, *pWcP, *pWhhP;
    float *pgi, *pgh, *ph0, *ph1, *pdeg, *pse, *pu1, *pu2;
    cudaGetSymbolAddress((void**)&phvP,  g_hvP);
    cudaGetSymbolAddress((void**)&pdhvP, g_dhvP);
    cudaGetSymbolAddress((void**)&pSP,   g_SP);
    cudaGetSymbolAddress((void**)&pWcP,  g_WcP);
    cudaGetSymbolAddress((void**)&pWhhP, g_WhhP);
    cudaGetSymbolAddress((void**)&pgi,  g_gi);
    cudaGetSymbolAddress((void**)&pgh,  g_gh);
    cudaGetSymbolAddress((void**)&ph0,  g_h0);
    cudaGetSymbolAddress((void**)&ph1,  g_h1);
    cudaGetSymbolAddress((void**)&pdeg, g_deg);
    cudaGetSymbolAddress((void**)&pse,  g_se);
    cudaGetSymbolAddress((void**)&pu1,  g_u1);
    cudaGetSymbolAddress((void**)&pu2,  g_u2);

    int nb = (N + 1023) / 1024;

    // fork: s2 = weight folds + packing; main = CSR build + split0
    cudaEventRecord(evStart, 0);
    cudaStreamWaitEvent(s2, evStart, 0);

    long wc_total = (long)T * H3 * H2;
    fold_wc_kernel<<<(int)((wc_total + 255) / 256), 256, 0, s2>>>(W_ih, W_msg, T);
    int packTot = T * H3 * 128 + T * H3 * 64;
    pack_w_kernel<<<(packTot + 255) / 256, 256, 0, s2>>>(W_hh, T);
    fold_u_kernel<<<(T * H3 + 255) / 256, 256, 0, s2>>>(W_ih, W_msg, b_msg, T);
    cudaEventRecord(evFold, s2);

    zero2_kernel<<<128, 256>>>(pdeg, pse, N);
    degse_kernel<<<(E + 255) / 256, 256>>>(dst, he, E);
    scan1_kernel<<<nb, 1024>>>(N);
    scan2_kernel<<<1, 32>>>(nb);
    scan3_kernel<<<nb, 1024>>>(N, E);
    fill_kernel<<<(E + 255) / 256, 256>>>(src, dst, E);
    split0_kernel<<<(N * 32 + 255) / 256, 256>>>(hv0, N);
    cudaEventRecord(evSplit0, 0);

    const float* cur = hv0;
    dim3 g1((N + 128 * TM - 1) / (128 * TM), 3);
    for (int t = 0; t < T; t++) {
        // main: gather (fp32 reads) -> gi GEMM ([dhv | S] @ Wc^T, K=256, packed)
        gather_kernel<<<(N * 32 + 255) / 256, 256>>>(cur, N);
        if (t == 0) cudaStreamWaitEvent(0, evFold, 0);
        mma_f16x3_a<true><<<g1, 256, GEMM_SMEM>>>(pdhvP, pSP, pWcP + (size_t)t * H3 * H2,
                                                  pgi, N, H3, H2);

        // s2: gh GEMM (hvP @ WhhP^T, K=128)
        cudaStreamWaitEvent(s2, (t == 0) ? evSplit0 : evGru, 0);
        mma_f16x3_a<false><<<g1, 256, GEMM_SMEM, s2>>>(phvP, nullptr,
                                                       pWhhP + (size_t)t * H3 * H,
                                                       pgh, N, H3, H);
        cudaEventRecord(evGh, s2);

        // join -> GRU on main
        cudaStreamWaitEvent(0, evGh, 0);
        float* outp = (t == T - 1) ? (float*)d_out : ((t & 1) ? ph1 : ph0);
        gru_kernel<<<(N * 32 + 255) / 256, 256>>>(cur, b_ih + (size_t)t * H3, b_hh + (size_t)t * H3,
                                                  pu1 + (size_t)t * H3, pu2 + (size_t)t * H3,
                                                  outp, (t < T - 1) ? 1 : 0, N);
        cudaEventRecord(evGru, 0);
        cur = outp;
    }
}